// round 14
// baseline (speedup 1.0000x reference)
#include <cuda_runtime.h>
#include <cuda_fp16.h>
#include <math.h>
#include <stdint.h>

#define Bn 4
#define T 1024
#define C 1024
#define H 16
#define HD 64
#define FF 4096
#define MROWS (Bn*T)   // 4096
#define NCONC 296      // 148 SMs x 2 CTAs

// ---------------- scratch (device globals; no runtime allocation) ----------------
__device__ __align__(1024) __half g_wqkvT[3*C * C];               // [3072,1024] W_qkv^T
__device__ __align__(1024) __half g_wprojT[C * C];                // [1024,1024] Wproj^T
__device__ __align__(1024) __half g_w1T[FF * C];                  // [4096,1024] W1^T
__device__ __align__(1024) __half g_w2T[C * FF];                  // [1024,4096] W2^T
__device__ __align__(1024) __half g_xn[MROWS * C];                // layernorm out
__device__ __align__(1024) __half g_qkv[(size_t)MROWS * 3 * C];   // [M, 3C]
__device__ __align__(1024) __half g_att[MROWS * C];               // attention out
__device__ __align__(1024) __half g_h[(size_t)MROWS * FF];        // FFN hidden
__device__ __align__(1024) float  g_x1[MROWS * C];                // x + attn_proj (fp32)

// ---------------- helpers ----------------
__device__ __forceinline__ uint32_t smem_u32(const void* p) {
    uint32_t a;
    asm("{ .reg .u64 t; cvta.to.shared.u64 t, %1; cvt.u32.u64 %0, t; }" : "=r"(a) : "l"(p));
    return a;
}

#define CP_ASYNC16(dst, src) \
    asm volatile("cp.async.cg.shared.global [%0], [%1], 16;" :: "r"(dst), "l"(src) : "memory")
#define CP_COMMIT() asm volatile("cp.async.commit_group;" ::: "memory")
#define CP_WAIT(n)  asm volatile("cp.async.wait_group %0;" :: "n"(n) : "memory")

#define LDSM4(r0, r1, r2, r3, addr) \
    asm volatile("ldmatrix.sync.aligned.m8n8.x4.shared.b16 {%0,%1,%2,%3}, [%4];" \
        : "=r"(r0), "=r"(r1), "=r"(r2), "=r"(r3) : "r"(addr))
#define LDSM4T(r0, r1, r2, r3, addr) \
    asm volatile("ldmatrix.sync.aligned.m8n8.x4.trans.shared.b16 {%0,%1,%2,%3}, [%4];" \
        : "=r"(r0), "=r"(r1), "=r"(r2), "=r"(r3) : "r"(addr))

__device__ __forceinline__ void mma_f16(float* d, const uint32_t* a, const uint32_t* b) {
    asm volatile(
        "mma.sync.aligned.m16n8k16.row.col.f32.f16.f16.f32 "
        "{%0,%1,%2,%3}, {%4,%5,%6,%7}, {%8,%9}, {%0,%1,%2,%3};"
        : "+f"(d[0]), "+f"(d[1]), "+f"(d[2]), "+f"(d[3])
        : "r"(a[0]), "r"(a[1]), "r"(a[2]), "r"(a[3]), "r"(b[0]), "r"(b[1]));
}
__device__ __forceinline__ uint32_t hmul2u(uint32_t a, uint32_t b) {
    __half2 r = __hmul2(*(__half2*)&a, *(__half2*)&b);
    return *(uint32_t*)&r;
}
__device__ __forceinline__ uint32_t f22h(float x, float y) {
    __half2 h = __floats2half2_rn(x, y);
    return *(uint32_t*)&h;
}

// ---------------- persistent fp16 tensor-core GEMM: C[M,N] = A[M,K] @ B[N,K]^T -------
// block tile 128x128x64 (BK=64), 256 threads / 8 warps (warp 64x32, 2x4),
// 3-stage cp.async, 2 CTAs/SM, ONE sync per k-tile, persistent tile loop over
// all (M/128)x(N/128) output tiles (removes wave quantization).
// EPI: 0 half out; 2 bias+gelu half out; 3 bias+resid(fp32) float out
#define PADH 72
#define STG 3
#define TILE_H (128 * PADH)
#define GEMM_SMEM (STG * 2 * TILE_H * 2)

template <int EPI>
__global__ __launch_bounds__(256, 2) void gemm_h(
    const __half* __restrict__ Ag, const __half* __restrict__ Bg, void* __restrict__ Cm,
    int Kn, int Nn, int Mn,
    const float* __restrict__ bias, const float* __restrict__ resid)
{
    extern __shared__ __half smh[];
    __half* smA = smh;                    // [STG][128][PADH]
    __half* smB = smh + STG * TILE_H;     // [STG][128][PADH]
    int tid = threadIdx.x, lane = tid & 31, wid = tid >> 5;
    int wm = (wid >> 2) * 64, wn = (wid & 3) * 32;
    int lane16 = lane & 15, lanehi = lane >> 4;
    int lq = lane >> 2, lr = lane & 3;

    const int NT = Kn >> 6;
    const int ntx = Nn >> 7;              // tiles along N
    const int ntiles = ntx * (Mn >> 7);
    int crow = tid >> 3, ccol = (tid & 7) * 8;

    int aoff = (wm + lane16) * PADH + lanehi * 8;
    int boff = (wn + lane16) * PADH + lanehi * 8;

    for (int tile = blockIdx.x; tile < ntiles; tile += gridDim.x) {
        int bx = tile % ntx, by = tile / ntx;

        auto issue = [&](int s, int kt) {
            const __half* As = Ag + (size_t)(by * 128) * Kn + kt * 64;
            const __half* Bs = Bg + (size_t)(bx * 128) * Kn + kt * 64;
            uint32_t dA = smem_u32(smA + s * TILE_H);
            uint32_t dB = smem_u32(smB + s * TILE_H);
            #pragma unroll
            for (int i = 0; i < 4; i++) {
                int r = crow + i * 32;
                CP_ASYNC16(dA + (r * PADH + ccol) * 2, As + (size_t)r * Kn + ccol);
                CP_ASYNC16(dB + (r * PADH + ccol) * 2, Bs + (size_t)r * Kn + ccol);
            }
        };

        float acc[4][4][4];
        #pragma unroll
        for (int mi = 0; mi < 4; mi++)
            #pragma unroll
            for (int ni = 0; ni < 4; ni++)
                #pragma unroll
                for (int q = 0; q < 4; q++) acc[mi][ni][q] = 0.f;

        #pragma unroll
        for (int s = 0; s < STG - 1; s++) { issue(s, s); CP_COMMIT(); }
        CP_WAIT(STG - 2);
        __syncthreads();                  // stage 0 ready

        for (int kt = 0; kt < NT; kt++) {
            int nx = kt + STG - 1;
            if (nx < NT) issue(nx % STG, nx);
            CP_COMMIT();

            const __half* At = smA + (kt % STG) * TILE_H;
            const __half* Bt = smB + (kt % STG) * TILE_H;

            #pragma unroll
            for (int ks = 0; ks < 4; ks++) {
                int k0 = ks * 16;
                uint32_t a[4][4], b[4][2];
                #pragma unroll
                for (int mi = 0; mi < 4; mi++) {
                    uint32_t ad = smem_u32(At + aoff + mi * 16 * PADH + k0);
                    LDSM4(a[mi][0], a[mi][1], a[mi][2], a[mi][3], ad);
                }
                #pragma unroll
                for (int nb = 0; nb < 2; nb++) {
                    uint32_t m0, m1, m2, m3;
                    uint32_t ad = smem_u32(Bt + boff + nb * 16 * PADH + k0);
                    LDSM4(m0, m1, m2, m3, ad);
                    b[2 * nb][0] = m0; b[2 * nb][1] = m2;
                    b[2 * nb + 1][0] = m1; b[2 * nb + 1][1] = m3;
                }
                #pragma unroll
                for (int mi = 0; mi < 4; mi++)
                    #pragma unroll
                    for (int ni = 0; ni < 4; ni++)
                        mma_f16(acc[mi][ni], a[mi], b[ni]);
            }

            CP_WAIT(STG - 2);
            __syncthreads();
        }

        // epilogue (no SMEM touched — safe to overlap with next tile's prologue timing)
        #pragma unroll
        for (int ni = 0; ni < 4; ni++) {
            int c = bx * 128 + wn + ni * 8 + lr * 2;
            float b0 = 0.f, b1 = 0.f;
            if (EPI >= 1) { b0 = bias[c]; b1 = bias[c + 1]; }
            #pragma unroll
            for (int mi = 0; mi < 4; mi++) {
                int r0 = by * 128 + wm + mi * 16 + lq;
                #pragma unroll
                for (int half_ = 0; half_ < 2; half_++) {
                    int r = r0 + half_ * 8;
                    float v0 = acc[mi][ni][half_ * 2 + 0] + b0;
                    float v1 = acc[mi][ni][half_ * 2 + 1] + b1;
                    if (EPI == 2) {
                        v0 = 0.5f * v0 * (1.0f + erff(v0 * 0.70710678118654752440f));
                        v1 = 0.5f * v1 * (1.0f + erff(v1 * 0.70710678118654752440f));
                    }
                    if (EPI == 3) {
                        float2 rr = *(const float2*)(resid + (size_t)r * Nn + c);
                        *(float2*)((float*)Cm + (size_t)r * Nn + c) = make_float2(v0 + rr.x, v1 + rr.y);
                    } else {
                        *(__half2*)((__half*)Cm + (size_t)r * Nn + c) = __floats2half2_rn(v0, v1);
                    }
                }
            }
        }
    }
}

static inline int gemm_grid(int Mn, int Nn) {
    int nt = (Mn / 128) * (Nn / 128);
    return nt < NCONC ? nt : NCONC;
}

// ---------------- fp16 flash attention (2 CTAs/SM, longest q-tiles first) ----------------
#define FQP 72
#define FKT (64 * FQP)
#define FLASH_SMEM ((128 * FQP + 2 * FKT + 2 * FKT) * 2)

__global__ __launch_bounds__(256, 2) void flash_h(const __half* __restrict__ qkv,
                                                  __half* __restrict__ att) {
    extern __shared__ __half smh[];
    __half* Qs = smh;
    __half* Ks = smh + 128 * FQP;
    __half* Vs = Ks + 2 * FKT;

    int tid = threadIdx.x, lane = tid & 31, w = tid >> 5;
    int lane16 = lane & 15, lanehi = lane >> 4;
    int lq = lane >> 2, lr = lane & 3;
    int qt = (int)(gridDim.x - 1 - blockIdx.x);
    int bh = blockIdx.y;
    int b = bh >> 4, h = bh & 15;
    const int ktiles = 2 * qt + 2;

    auto issueQ = [&]() {
        uint32_t dQ = smem_u32(Qs);
        #pragma unroll
        for (int i = 0; i < 4; i++) {
            int c = tid + i * 256;
            int row = c >> 3, col = (c & 7) * 8;
            const __half* src = qkv + (size_t)(b * T + qt * 128 + row) * 3072 + h * 64 + col;
            CP_ASYNC16(dQ + (row * FQP + col) * 2, src);
        }
    };
    auto issueKV = [&](int kt, int buf) {
        uint32_t dK = smem_u32(Ks + buf * FKT);
        uint32_t dV = smem_u32(Vs + buf * FKT);
        #pragma unroll
        for (int i = 0; i < 2; i++) {
            int c = tid + i * 256;
            int row = c >> 3, col = (c & 7) * 8;
            size_t gr = (size_t)(b * T + kt * 64 + row) * 3072 + h * 64 + col;
            CP_ASYNC16(dK + (row * FQP + col) * 2, qkv + gr + 1024);
            CP_ASYNC16(dV + (row * FQP + col) * 2, qkv + gr + 2048);
        }
    };

    issueQ(); issueKV(0, 0); CP_COMMIT();
    issueKV(1, 1); CP_COMMIT();
    CP_WAIT(1);
    __syncthreads();

    uint32_t qf[4][4];
    {
        __half2 s8 = __float2half2_rn(0.125f);
        uint32_t s8u = *(uint32_t*)&s8;
        #pragma unroll
        for (int ks = 0; ks < 4; ks++) {
            uint32_t ad = smem_u32(Qs + (w * 16 + lane16) * FQP + ks * 16 + lanehi * 8);
            LDSM4(qf[ks][0], qf[ks][1], qf[ks][2], qf[ks][3], ad);
            #pragma unroll
            for (int j = 0; j < 4; j++) qf[ks][j] = hmul2u(qf[ks][j], s8u);
        }
    }

    float oacc[8][4];
    #pragma unroll
    for (int ni = 0; ni < 8; ni++)
        #pragma unroll
        for (int q = 0; q < 4; q++) oacc[ni][q] = 0.f;
    float m0 = -1e30f, m1 = -1e30f, l0 = 0.f, l1 = 0.f;

    const int gr0 = qt * 128 + w * 16 + lq;
    const int gr1 = gr0 + 8;

    for (int kt = 0; kt < ktiles; kt++) {
        if (kt > 0) { CP_WAIT(1); __syncthreads(); }
        const __half* K = Ks + (kt & 1) * FKT;
        const __half* V = Vs + (kt & 1) * FKT;

        float sacc[8][4];
        #pragma unroll
        for (int ni = 0; ni < 8; ni++)
            #pragma unroll
            for (int q = 0; q < 4; q++) sacc[ni][q] = 0.f;
        #pragma unroll
        for (int ks = 0; ks < 4; ks++) {
            int k0 = ks * 16;
            #pragma unroll
            for (int nb = 0; nb < 4; nb++) {
                uint32_t m0r, m1r, m2r, m3r;
                uint32_t ad = smem_u32(K + (nb * 16 + lane16) * FQP + k0 + lanehi * 8);
                LDSM4(m0r, m1r, m2r, m3r, ad);
                uint32_t blo[2] = {m0r, m2r}, bhi[2] = {m1r, m3r};
                mma_f16(sacc[2 * nb], qf[ks], blo);
                mma_f16(sacc[2 * nb + 1], qf[ks], bhi);
            }
        }

        if (kt >= 2 * qt) {
            #pragma unroll
            for (int ni = 0; ni < 8; ni++) {
                int cbase = kt * 64 + ni * 8 + lr * 2;
                #pragma unroll
                for (int j = 0; j < 2; j++) {
                    if (cbase + j > gr0) sacc[ni][j]     = -1e30f;
                    if (cbase + j > gr1) sacc[ni][2 + j] = -1e30f;
                }
            }
        }

        float mx0 = -1e30f, mx1 = -1e30f;
        #pragma unroll
        for (int ni = 0; ni < 8; ni++) {
            mx0 = fmaxf(mx0, fmaxf(sacc[ni][0], sacc[ni][1]));
            mx1 = fmaxf(mx1, fmaxf(sacc[ni][2], sacc[ni][3]));
        }
        #pragma unroll
        for (int off = 1; off <= 2; off <<= 1) {
            mx0 = fmaxf(mx0, __shfl_xor_sync(0xffffffffu, mx0, off));
            mx1 = fmaxf(mx1, __shfl_xor_sync(0xffffffffu, mx1, off));
        }
        float mn0 = fmaxf(m0, mx0), mn1 = fmaxf(m1, mx1);
        float al0 = __expf(m0 - mn0), al1 = __expf(m1 - mn1);
        m0 = mn0; m1 = mn1;
        float s0 = 0.f, s1 = 0.f;
        #pragma unroll
        for (int ni = 0; ni < 8; ni++) {
            sacc[ni][0] = __expf(sacc[ni][0] - mn0);
            sacc[ni][1] = __expf(sacc[ni][1] - mn0);
            sacc[ni][2] = __expf(sacc[ni][2] - mn1);
            sacc[ni][3] = __expf(sacc[ni][3] - mn1);
            s0 += sacc[ni][0] + sacc[ni][1];
            s1 += sacc[ni][2] + sacc[ni][3];
        }
        #pragma unroll
        for (int off = 1; off <= 2; off <<= 1) {
            s0 += __shfl_xor_sync(0xffffffffu, s0, off);
            s1 += __shfl_xor_sync(0xffffffffu, s1, off);
        }
        l0 = l0 * al0 + s0;
        l1 = l1 * al1 + s1;
        #pragma unroll
        for (int ni = 0; ni < 8; ni++) {
            oacc[ni][0] *= al0; oacc[ni][1] *= al0;
            oacc[ni][2] *= al1; oacc[ni][3] *= al1;
        }

        #pragma unroll
        for (int kk = 0; kk < 4; kk++) {
            uint32_t a[4];
            a[0] = f22h(sacc[2 * kk][0], sacc[2 * kk][1]);
            a[1] = f22h(sacc[2 * kk][2], sacc[2 * kk][3]);
            a[2] = f22h(sacc[2 * kk + 1][0], sacc[2 * kk + 1][1]);
            a[3] = f22h(sacc[2 * kk + 1][2], sacc[2 * kk + 1][3]);
            #pragma unroll
            for (int dbp = 0; dbp < 4; dbp++) {
                uint32_t m0r, m1r, m2r, m3r;
                uint32_t ad = smem_u32(V + (kk * 16 + lane16) * FQP + dbp * 16 + lanehi * 8);
                LDSM4T(m0r, m1r, m2r, m3r, ad);
                uint32_t blo[2] = {m0r, m1r}, bhi[2] = {m2r, m3r};
                mma_f16(oacc[2 * dbp], a, blo);
                mma_f16(oacc[2 * dbp + 1], a, bhi);
            }
        }

        __syncthreads();
        if (kt + 2 < ktiles) issueKV(kt + 2, kt & 1);
        CP_COMMIT();
    }

    float inv0 = 1.0f / l0, inv1 = 1.0f / l1;
    size_t ro0 = ((size_t)(b * T) + gr0) * 1024 + h * 64;
    size_t ro1 = ((size_t)(b * T) + gr1) * 1024 + h * 64;
    #pragma unroll
    for (int ni = 0; ni < 8; ni++) {
        int cc = ni * 8 + lr * 2;
        *(__half2*)(att + ro0 + cc) = __floats2half2_rn(oacc[ni][0] * inv0, oacc[ni][1] * inv0);
        *(__half2*)(att + ro1 + cc) = __floats2half2_rn(oacc[ni][2] * inv1, oacc[ni][3] * inv1);
    }
}

// ---------------- LN body (device) ----------------
__device__ __forceinline__ void ln_body(const float* xr, const float* g, const float* b,
                                        __half* yr, float* sh, int tid) {
    float s = 0.f, s2 = 0.f;
    for (int i = tid; i < C; i += 256) {
        float v = xr[i]; s += v; s2 += v * v;
    }
    int lid = tid & 31, wid = tid >> 5;
    #pragma unroll
    for (int o = 16; o > 0; o >>= 1) {
        s  += __shfl_xor_sync(0xffffffffu, s,  o);
        s2 += __shfl_xor_sync(0xffffffffu, s2, o);
    }
    if (lid == 0) { sh[wid] = s; sh[wid + 32] = s2; }
    __syncthreads();
    if (tid == 0) {
        float a = 0.f, a2 = 0.f;
        for (int w = 0; w < 8; w++) { a += sh[w]; a2 += sh[w + 32]; }
        sh[0] = a; sh[1] = a2;
    }
    __syncthreads();
    float mean = sh[0] * (1.0f / C);
    float var  = sh[1] * (1.0f / C) - mean * mean;
    float rstd = rsqrtf(var + 1e-5f);
    for (int i = tid; i < C; i += 256)
        yr[i] = __float2half_rn((xr[i] - mean) * rstd * g[i] + b[i]);
}

// ---------------- transpose body (device): src[K,N] fp32 -> dst[N,K] half ----------------
__device__ __forceinline__ void tr_body(const float* src, __half* dst, int Kn, int Nn,
                                        int bx, int by, int tid, float (*tile)[33]) {
    int k0 = by * 32, n0 = bx * 32;
    int tx = tid & 31, ty = tid >> 5;
    #pragma unroll
    for (int r = ty; r < 32; r += 8)
        tile[r][tx] = src[(size_t)(k0 + r) * Nn + n0 + tx];
    __syncthreads();
    #pragma unroll
    for (int r = ty; r < 32; r += 8)
        dst[(size_t)(n0 + r) * Kn + k0 + tx] = __float2half_rn(tile[tx][r]);
}

// ---------------- fused prep: LN1 + coalesced qkv pack + 3 weight transposes ----------
__global__ __launch_bounds__(256) void prep_k(
    const float* __restrict__ x, const float* __restrict__ ln1_g, const float* __restrict__ ln1_b,
    const float* __restrict__ Wq, const float* __restrict__ Wk, const float* __restrict__ Wv,
    const float* __restrict__ Wproj, const float* __restrict__ W1, const float* __restrict__ W2)
{
    __shared__ float tile[32][33];
    __shared__ float sh[64];
    int tid = threadIdx.x;
    int bid = blockIdx.x;

    if (bid < MROWS) {
        ln_body(x + (size_t)bid * C, ln1_g, ln1_b, g_xn + (size_t)bid * C, sh, tid);
    } else if (bid < MROWS + 3072) {
        int b2 = bid - MROWS;
        int mat = b2 >> 10;
        int rem = b2 & 1023;
        int h = rem >> 6;
        int kt = (rem & 63) >> 1;
        int dt = rem & 1;
        const float* W = (mat == 0) ? Wq : (mat == 1) ? Wk : Wv;
        int k0 = kt * 32, d0 = dt * 32;
        int tx = tid & 31, ty = tid >> 5;
        #pragma unroll
        for (int r = ty; r < 32; r += 8)
            tile[r][tx] = W[((size_t)h * C + k0 + r) * HD + d0 + tx];
        __syncthreads();
        #pragma unroll
        for (int r = ty; r < 32; r += 8) {
            int n = mat * 1024 + h * 64 + d0 + r;
            g_wqkvT[(size_t)n * C + k0 + tx] = __float2half_rn(tile[tx][r]);
        }
    } else if (bid < MROWS + 3072 + 1024) {
        int b2 = bid - (MROWS + 3072);
        tr_body(Wproj, g_wprojT, C, C, b2 & 31, b2 >> 5, tid, tile);
    } else if (bid < MROWS + 3072 + 1024 + 4096) {
        int b2 = bid - (MROWS + 3072 + 1024);
        tr_body(W1, g_w1T, C, FF, b2 & 127, b2 >> 7, tid, tile);
    } else {
        int b2 = bid - (MROWS + 3072 + 1024 + 4096);
        tr_body(W2, g_w2T, FF, C, b2 & 31, b2 >> 5, tid, tile);
    }
}
#define PREP_BLOCKS (MROWS + 3072 + 1024 + 4096 + 4096)

// ---------------- standalone LN (for LN2) ----------------
__global__ void layernorm_k(const float* __restrict__ x, const float* __restrict__ g,
                            const float* __restrict__ b, __half* __restrict__ out) {
    __shared__ float sh[64];
    ln_body(x + (size_t)blockIdx.x * C, g, b, out + (size_t)blockIdx.x * C, sh, threadIdx.x);
}

// ---------------- launch ----------------
extern "C" void kernel_launch(void* const* d_in, const int* in_sizes, int n_in,
                              void* d_out, int out_size) {
    const float* x      = (const float*)d_in[0];
    const float* ln1_g  = (const float*)d_in[1];
    const float* ln1_b  = (const float*)d_in[2];
    const float* ln2_g  = (const float*)d_in[3];
    const float* ln2_b  = (const float*)d_in[4];
    const float* Wq     = (const float*)d_in[5];
    const float* Wk     = (const float*)d_in[6];
    const float* Wv     = (const float*)d_in[7];
    const float* Wproj  = (const float*)d_in[8];
    const float* bproj  = (const float*)d_in[9];
    const float* W1     = (const float*)d_in[10];
    const float* b1     = (const float*)d_in[11];
    const float* W2     = (const float*)d_in[12];
    const float* b2     = (const float*)d_in[13];
    float* out = (float*)d_out;

    __half *p_wqkvT, *p_wprojT, *p_w1T, *p_w2T, *p_xn, *p_qkv, *p_att, *p_h;
    float* p_x1;
    cudaGetSymbolAddress((void**)&p_wqkvT,  g_wqkvT);
    cudaGetSymbolAddress((void**)&p_wprojT, g_wprojT);
    cudaGetSymbolAddress((void**)&p_w1T,    g_w1T);
    cudaGetSymbolAddress((void**)&p_w2T,    g_w2T);
    cudaGetSymbolAddress((void**)&p_xn,     g_xn);
    cudaGetSymbolAddress((void**)&p_qkv,    g_qkv);
    cudaGetSymbolAddress((void**)&p_att,    g_att);
    cudaGetSymbolAddress((void**)&p_x1,     g_x1);
    cudaGetSymbolAddress((void**)&p_h,      g_h);

    cudaFuncSetAttribute(gemm_h<0>, cudaFuncAttributeMaxDynamicSharedMemorySize, GEMM_SMEM);
    cudaFuncSetAttribute(gemm_h<2>, cudaFuncAttributeMaxDynamicSharedMemorySize, GEMM_SMEM);
    cudaFuncSetAttribute(gemm_h<3>, cudaFuncAttributeMaxDynamicSharedMemorySize, GEMM_SMEM);
    cudaFuncSetAttribute(flash_h,   cudaFuncAttributeMaxDynamicSharedMemorySize, FLASH_SMEM);

    // 1) fused prep: LN1 + coalesced pack + all weight transposes
    prep_k<<<PREP_BLOCKS, 256>>>(x, ln1_g, ln1_b, Wq, Wk, Wv, Wproj, W1, W2);
    // 2) QKV GEMM (persistent): [4096,1024] @ [1024,3072] -> half
    gemm_h<0><<<gemm_grid(MROWS, 3 * C), 256, GEMM_SMEM>>>(
        p_xn, p_wqkvT, p_qkv, C, 3 * C, MROWS, nullptr, nullptr);
    // 3) fused flash attention -> att (half), longest tiles first
    flash_h<<<dim3(T / 128, Bn * H), 256, FLASH_SMEM>>>(p_qkv, p_att);
    // 4) proj + bias + residual(x) -> x1 (fp32)
    gemm_h<3><<<gemm_grid(MROWS, C), 256, GEMM_SMEM>>>(
        p_att, p_wprojT, p_x1, C, C, MROWS, bproj, x);
    // 5) LN2 -> xn (half)
    layernorm_k<<<MROWS, 256>>>(p_x1, ln2_g, ln2_b, p_xn);
    // 6) FFN1 + bias + gelu -> h (half), persistent
    gemm_h<2><<<gemm_grid(MROWS, FF), 256, GEMM_SMEM>>>(
        p_xn, p_w1T, p_h, C, FF, MROWS, b1, nullptr);
    // 7) FFN2 + bias + residual(x1) -> out (fp32)
    gemm_h<3><<<gemm_grid(MROWS, C), 256, GEMM_SMEM>>>(
        p_h, p_w2T, out, FF, C, MROWS, b2, p_x1);
}

// round 15
// speedup vs baseline: 1.0433x; 1.0433x over previous
#include <cuda_runtime.h>
#include <cuda_fp16.h>
#include <math.h>
#include <stdint.h>

#define Bn 4
#define T 1024
#define C 1024
#define H 16
#define HD 64
#define FF 4096
#define MROWS (Bn*T)   // 4096

// ---------------- scratch (device globals; no runtime allocation) ----------------
__device__ __align__(1024) __half g_wqkvT[3*C * C];               // [3072,1024] W_qkv^T
__device__ __align__(1024) __half g_wprojT[C * C];                // [1024,1024] Wproj^T
__device__ __align__(1024) __half g_w1T[FF * C];                  // [4096,1024] W1^T
__device__ __align__(1024) __half g_w2T[C * FF];                  // [1024,4096] W2^T
__device__ __align__(1024) __half g_xn[MROWS * C];                // layernorm out
__device__ __align__(1024) __half g_qkv[(size_t)MROWS * 3 * C];   // [M, 3C]
__device__ __align__(1024) __half g_att[MROWS * C];               // attention out
__device__ __align__(1024) __half g_h[(size_t)MROWS * FF];        // FFN hidden
__device__ __align__(1024) float  g_x1[MROWS * C];                // x + attn_proj (fp32)

// ---------------- helpers ----------------
__device__ __forceinline__ uint32_t smem_u32(const void* p) {
    uint32_t a;
    asm("{ .reg .u64 t; cvta.to.shared.u64 t, %1; cvt.u32.u64 %0, t; }" : "=r"(a) : "l"(p));
    return a;
}

#define CP_ASYNC16(dst, src) \
    asm volatile("cp.async.cg.shared.global [%0], [%1], 16;" :: "r"(dst), "l"(src) : "memory")
#define CP_COMMIT() asm volatile("cp.async.commit_group;" ::: "memory")
#define CP_WAIT(n)  asm volatile("cp.async.wait_group %0;" :: "n"(n) : "memory")

#define LDSM4(r0, r1, r2, r3, addr) \
    asm volatile("ldmatrix.sync.aligned.m8n8.x4.shared.b16 {%0,%1,%2,%3}, [%4];" \
        : "=r"(r0), "=r"(r1), "=r"(r2), "=r"(r3) : "r"(addr))
#define LDSM4T(r0, r1, r2, r3, addr) \
    asm volatile("ldmatrix.sync.aligned.m8n8.x4.trans.shared.b16 {%0,%1,%2,%3}, [%4];" \
        : "=r"(r0), "=r"(r1), "=r"(r2), "=r"(r3) : "r"(addr))

__device__ __forceinline__ void mma_f16(float* d, const uint32_t* a, const uint32_t* b) {
    asm volatile(
        "mma.sync.aligned.m16n8k16.row.col.f32.f16.f16.f32 "
        "{%0,%1,%2,%3}, {%4,%5,%6,%7}, {%8,%9}, {%0,%1,%2,%3};"
        : "+f"(d[0]), "+f"(d[1]), "+f"(d[2]), "+f"(d[3])
        : "r"(a[0]), "r"(a[1]), "r"(a[2]), "r"(a[3]), "r"(b[0]), "r"(b[1]));
}
__device__ __forceinline__ uint32_t hmul2u(uint32_t a, uint32_t b) {
    __half2 r = __hmul2(*(__half2*)&a, *(__half2*)&b);
    return *(uint32_t*)&r;
}
__device__ __forceinline__ uint32_t f22h(float x, float y) {
    __half2 h = __floats2half2_rn(x, y);
    return *(uint32_t*)&h;
}

// ---------------- fp16 tensor-core GEMM: C[M,N] = A[M,K] @ B[N,K]^T ----------------
// block tile 128x128x64 (BK=64), 256 threads / 8 warps (warp 64x32, 2x4),
// 3-stage cp.async, 2 CTAs/SM, ONE sync per k-tile.  (R13 configuration — best)
// EPI: 0 half out; 2 bias+gelu half out; 3 bias+resid(fp32) float out
#define PADH 72
#define STG 3
#define TILE_H (128 * PADH)
#define GEMM_SMEM (STG * 2 * TILE_H * 2)

template <int EPI>
__global__ __launch_bounds__(256, 2) void gemm_h(
    const __half* __restrict__ Ag, const __half* __restrict__ Bg, void* __restrict__ Cm,
    int Kn, int Nn,
    const float* __restrict__ bias, const float* __restrict__ resid)
{
    extern __shared__ __half smh[];
    __half* smA = smh;                    // [STG][128][PADH]
    __half* smB = smh + STG * TILE_H;     // [STG][128][PADH]
    int tid = threadIdx.x, lane = tid & 31, wid = tid >> 5;
    int bx = blockIdx.x, by = blockIdx.y;
    int wm = (wid >> 2) * 64, wn = (wid & 3) * 32;
    int lane16 = lane & 15, lanehi = lane >> 4;
    int lq = lane >> 2, lr = lane & 3;

    const int NT = Kn >> 6;
    int crow = tid >> 3, ccol = (tid & 7) * 8;

    auto issue = [&](int s, int kt) {
        const __half* As = Ag + (size_t)(by * 128) * Kn + kt * 64;
        const __half* Bs = Bg + (size_t)(bx * 128) * Kn + kt * 64;
        uint32_t dA = smem_u32(smA + s * TILE_H);
        uint32_t dB = smem_u32(smB + s * TILE_H);
        #pragma unroll
        for (int i = 0; i < 4; i++) {
            int r = crow + i * 32;
            CP_ASYNC16(dA + (r * PADH + ccol) * 2, As + (size_t)r * Kn + ccol);
            CP_ASYNC16(dB + (r * PADH + ccol) * 2, Bs + (size_t)r * Kn + ccol);
        }
    };

    float acc[4][4][4];
    #pragma unroll
    for (int mi = 0; mi < 4; mi++)
        #pragma unroll
        for (int ni = 0; ni < 4; ni++)
            #pragma unroll
            for (int q = 0; q < 4; q++) acc[mi][ni][q] = 0.f;

    #pragma unroll
    for (int s = 0; s < STG - 1; s++) { issue(s, s); CP_COMMIT(); }
    CP_WAIT(STG - 2);
    __syncthreads();

    int aoff = (wm + lane16) * PADH + lanehi * 8;
    int boff = (wn + lane16) * PADH + lanehi * 8;

    for (int kt = 0; kt < NT; kt++) {
        int nx = kt + STG - 1;
        if (nx < NT) issue(nx % STG, nx);
        CP_COMMIT();

        const __half* At = smA + (kt % STG) * TILE_H;
        const __half* Bt = smB + (kt % STG) * TILE_H;

        #pragma unroll
        for (int ks = 0; ks < 4; ks++) {
            int k0 = ks * 16;
            uint32_t a[4][4], b[4][2];
            #pragma unroll
            for (int mi = 0; mi < 4; mi++) {
                uint32_t ad = smem_u32(At + aoff + mi * 16 * PADH + k0);
                LDSM4(a[mi][0], a[mi][1], a[mi][2], a[mi][3], ad);
            }
            #pragma unroll
            for (int nb = 0; nb < 2; nb++) {
                uint32_t m0, m1, m2, m3;
                uint32_t ad = smem_u32(Bt + boff + nb * 16 * PADH + k0);
                LDSM4(m0, m1, m2, m3, ad);
                b[2 * nb][0] = m0; b[2 * nb][1] = m2;
                b[2 * nb + 1][0] = m1; b[2 * nb + 1][1] = m3;
            }
            #pragma unroll
            for (int mi = 0; mi < 4; mi++)
                #pragma unroll
                for (int ni = 0; ni < 4; ni++)
                    mma_f16(acc[mi][ni], a[mi], b[ni]);
        }

        CP_WAIT(STG - 2);
        __syncthreads();
    }

    #pragma unroll
    for (int ni = 0; ni < 4; ni++) {
        int c = bx * 128 + wn + ni * 8 + lr * 2;
        float b0 = 0.f, b1 = 0.f;
        if (EPI >= 1) { b0 = bias[c]; b1 = bias[c + 1]; }
        #pragma unroll
        for (int mi = 0; mi < 4; mi++) {
            int r0 = by * 128 + wm + mi * 16 + lq;
            #pragma unroll
            for (int half_ = 0; half_ < 2; half_++) {
                int r = r0 + half_ * 8;
                float v0 = acc[mi][ni][half_ * 2 + 0] + b0;
                float v1 = acc[mi][ni][half_ * 2 + 1] + b1;
                if (EPI == 2) {
                    v0 = 0.5f * v0 * (1.0f + erff(v0 * 0.70710678118654752440f));
                    v1 = 0.5f * v1 * (1.0f + erff(v1 * 0.70710678118654752440f));
                }
                if (EPI == 3) {
                    float2 rr = *(const float2*)(resid + (size_t)r * Nn + c);
                    *(float2*)((float*)Cm + (size_t)r * Nn + c) = make_float2(v0 + rr.x, v1 + rr.y);
                } else {
                    *(__half2*)((__half*)Cm + (size_t)r * Nn + c) = __floats2half2_rn(v0, v1);
                }
            }
        }
    }
}

// ---------------- fp16 flash attention: 3-buffer K/V, ONE sync per k-tile ------------
#define FQP 72
#define FKT (64 * FQP)
#define FLASH_SMEM ((128 * FQP + 3 * FKT + 3 * FKT) * 2)

__global__ __launch_bounds__(256, 2) void flash_h(const __half* __restrict__ qkv,
                                                  __half* __restrict__ att) {
    extern __shared__ __half smh[];
    __half* Qs = smh;                    // [128][FQP]
    __half* Ks = smh + 128 * FQP;        // [3][64][FQP]
    __half* Vs = Ks + 3 * FKT;           // [3][64][FQP]

    int tid = threadIdx.x, lane = tid & 31, w = tid >> 5;
    int lane16 = lane & 15, lanehi = lane >> 4;
    int lq = lane >> 2, lr = lane & 3;
    int qt = (int)(gridDim.x - 1 - blockIdx.x);   // longest CTAs first
    int bh = blockIdx.y;
    int b = bh >> 4, h = bh & 15;
    const int ktiles = 2 * qt + 2;

    auto issueQ = [&]() {
        uint32_t dQ = smem_u32(Qs);
        #pragma unroll
        for (int i = 0; i < 4; i++) {
            int c = tid + i * 256;
            int row = c >> 3, col = (c & 7) * 8;
            const __half* src = qkv + (size_t)(b * T + qt * 128 + row) * 3072 + h * 64 + col;
            CP_ASYNC16(dQ + (row * FQP + col) * 2, src);
        }
    };
    auto issueKV = [&](int kt, int buf) {
        uint32_t dK = smem_u32(Ks + buf * FKT);
        uint32_t dV = smem_u32(Vs + buf * FKT);
        #pragma unroll
        for (int i = 0; i < 2; i++) {
            int c = tid + i * 256;
            int row = c >> 3, col = (c & 7) * 8;
            size_t gr = (size_t)(b * T + kt * 64 + row) * 3072 + h * 64 + col;
            CP_ASYNC16(dK + (row * FQP + col) * 2, qkv + gr + 1024);
            CP_ASYNC16(dV + (row * FQP + col) * 2, qkv + gr + 2048);
        }
    };

    // prologue: Q + KV0 in group0, KV1 in group1
    issueQ(); issueKV(0, 0); CP_COMMIT();
    issueKV(1, 1); CP_COMMIT();
    CP_WAIT(1);
    __syncthreads();   // Q + KV0 ready

    uint32_t qf[4][4];
    {
        __half2 s8 = __float2half2_rn(0.125f);
        uint32_t s8u = *(uint32_t*)&s8;
        #pragma unroll
        for (int ks = 0; ks < 4; ks++) {
            uint32_t ad = smem_u32(Qs + (w * 16 + lane16) * FQP + ks * 16 + lanehi * 8);
            LDSM4(qf[ks][0], qf[ks][1], qf[ks][2], qf[ks][3], ad);
            #pragma unroll
            for (int j = 0; j < 4; j++) qf[ks][j] = hmul2u(qf[ks][j], s8u);
        }
    }

    float oacc[8][4];
    #pragma unroll
    for (int ni = 0; ni < 8; ni++)
        #pragma unroll
        for (int q = 0; q < 4; q++) oacc[ni][q] = 0.f;
    float m0 = -1e30f, m1 = -1e30f, l0 = 0.f, l1 = 0.f;

    const int gr0 = qt * 128 + w * 16 + lq;
    const int gr1 = gr0 + 8;

    for (int kt = 0; kt < ktiles; kt++) {
        if (kt > 0) { CP_WAIT(1); __syncthreads(); }   // KV[kt] ready, all reads of kt-1 done
        // prefetch kt+2 into buffer (kt+2)%3 — disjoint from kt%3 (reading) and (kt+1)%3
        if (kt + 2 < ktiles) issueKV(kt + 2, (kt + 2) % 3);
        CP_COMMIT();

        const __half* K = Ks + (kt % 3) * FKT;
        const __half* V = Vs + (kt % 3) * FKT;

        float sacc[8][4];
        #pragma unroll
        for (int ni = 0; ni < 8; ni++)
            #pragma unroll
            for (int q = 0; q < 4; q++) sacc[ni][q] = 0.f;
        #pragma unroll
        for (int ks = 0; ks < 4; ks++) {
            int k0 = ks * 16;
            #pragma unroll
            for (int nb = 0; nb < 4; nb++) {
                uint32_t m0r, m1r, m2r, m3r;
                uint32_t ad = smem_u32(K + (nb * 16 + lane16) * FQP + k0 + lanehi * 8);
                LDSM4(m0r, m1r, m2r, m3r, ad);
                uint32_t blo[2] = {m0r, m2r}, bhi[2] = {m1r, m3r};
                mma_f16(sacc[2 * nb], qf[ks], blo);
                mma_f16(sacc[2 * nb + 1], qf[ks], bhi);
            }
        }

        if (kt >= 2 * qt) {
            #pragma unroll
            for (int ni = 0; ni < 8; ni++) {
                int cbase = kt * 64 + ni * 8 + lr * 2;
                #pragma unroll
                for (int j = 0; j < 2; j++) {
                    if (cbase + j > gr0) sacc[ni][j]     = -1e30f;
                    if (cbase + j > gr1) sacc[ni][2 + j] = -1e30f;
                }
            }
        }

        float mx0 = -1e30f, mx1 = -1e30f;
        #pragma unroll
        for (int ni = 0; ni < 8; ni++) {
            mx0 = fmaxf(mx0, fmaxf(sacc[ni][0], sacc[ni][1]));
            mx1 = fmaxf(mx1, fmaxf(sacc[ni][2], sacc[ni][3]));
        }
        #pragma unroll
        for (int off = 1; off <= 2; off <<= 1) {
            mx0 = fmaxf(mx0, __shfl_xor_sync(0xffffffffu, mx0, off));
            mx1 = fmaxf(mx1, __shfl_xor_sync(0xffffffffu, mx1, off));
        }
        float mn0 = fmaxf(m0, mx0), mn1 = fmaxf(m1, mx1);
        float al0 = __expf(m0 - mn0), al1 = __expf(m1 - mn1);
        m0 = mn0; m1 = mn1;
        float s0 = 0.f, s1 = 0.f;
        #pragma unroll
        for (int ni = 0; ni < 8; ni++) {
            sacc[ni][0] = __expf(sacc[ni][0] - mn0);
            sacc[ni][1] = __expf(sacc[ni][1] - mn0);
            sacc[ni][2] = __expf(sacc[ni][2] - mn1);
            sacc[ni][3] = __expf(sacc[ni][3] - mn1);
            s0 += sacc[ni][0] + sacc[ni][1];
            s1 += sacc[ni][2] + sacc[ni][3];
        }
        #pragma unroll
        for (int off = 1; off <= 2; off <<= 1) {
            s0 += __shfl_xor_sync(0xffffffffu, s0, off);
            s1 += __shfl_xor_sync(0xffffffffu, s1, off);
        }
        l0 = l0 * al0 + s0;
        l1 = l1 * al1 + s1;
        #pragma unroll
        for (int ni = 0; ni < 8; ni++) {
            oacc[ni][0] *= al0; oacc[ni][1] *= al0;
            oacc[ni][2] *= al1; oacc[ni][3] *= al1;
        }

        #pragma unroll
        for (int kk = 0; kk < 4; kk++) {
            uint32_t a[4];
            a[0] = f22h(sacc[2 * kk][0], sacc[2 * kk][1]);
            a[1] = f22h(sacc[2 * kk][2], sacc[2 * kk][3]);
            a[2] = f22h(sacc[2 * kk + 1][0], sacc[2 * kk + 1][1]);
            a[3] = f22h(sacc[2 * kk + 1][2], sacc[2 * kk + 1][3]);
            #pragma unroll
            for (int dbp = 0; dbp < 4; dbp++) {
                uint32_t m0r, m1r, m2r, m3r;
                uint32_t ad = smem_u32(V + (kk * 16 + lane16) * FQP + dbp * 16 + lanehi * 8);
                LDSM4T(m0r, m1r, m2r, m3r, ad);
                uint32_t blo[2] = {m0r, m1r}, bhi[2] = {m2r, m3r};
                mma_f16(oacc[2 * dbp], a, blo);
                mma_f16(oacc[2 * dbp + 1], a, bhi);
            }
        }
        // no second sync: next iteration's top sync covers buffer-reuse safety
    }

    float inv0 = 1.0f / l0, inv1 = 1.0f / l1;
    size_t ro0 = ((size_t)(b * T) + gr0) * 1024 + h * 64;
    size_t ro1 = ((size_t)(b * T) + gr1) * 1024 + h * 64;
    #pragma unroll
    for (int ni = 0; ni < 8; ni++) {
        int cc = ni * 8 + lr * 2;
        *(__half2*)(att + ro0 + cc) = __floats2half2_rn(oacc[ni][0] * inv0, oacc[ni][1] * inv0);
        *(__half2*)(att + ro1 + cc) = __floats2half2_rn(oacc[ni][2] * inv1, oacc[ni][3] * inv1);
    }
}

// ---------------- LN body (device) ----------------
__device__ __forceinline__ void ln_body(const float* xr, const float* g, const float* b,
                                        __half* yr, float* sh, int tid) {
    float s = 0.f, s2 = 0.f;
    for (int i = tid; i < C; i += 256) {
        float v = xr[i]; s += v; s2 += v * v;
    }
    int lid = tid & 31, wid = tid >> 5;
    #pragma unroll
    for (int o = 16; o > 0; o >>= 1) {
        s  += __shfl_xor_sync(0xffffffffu, s,  o);
        s2 += __shfl_xor_sync(0xffffffffu, s2, o);
    }
    if (lid == 0) { sh[wid] = s; sh[wid + 32] = s2; }
    __syncthreads();
    if (tid == 0) {
        float a = 0.f, a2 = 0.f;
        for (int w = 0; w < 8; w++) { a += sh[w]; a2 += sh[w + 32]; }
        sh[0] = a; sh[1] = a2;
    }
    __syncthreads();
    float mean = sh[0] * (1.0f / C);
    float var  = sh[1] * (1.0f / C) - mean * mean;
    float rstd = rsqrtf(var + 1e-5f);
    for (int i = tid; i < C; i += 256)
        yr[i] = __float2half_rn((xr[i] - mean) * rstd * g[i] + b[i]);
}

// ---------------- transpose body (device): src[K,N] fp32 -> dst[N,K] half ----------------
__device__ __forceinline__ void tr_body(const float* src, __half* dst, int Kn, int Nn,
                                        int bx, int by, int tid, float (*tile)[33]) {
    int k0 = by * 32, n0 = bx * 32;
    int tx = tid & 31, ty = tid >> 5;
    #pragma unroll
    for (int r = ty; r < 32; r += 8)
        tile[r][tx] = src[(size_t)(k0 + r) * Nn + n0 + tx];
    __syncthreads();
    #pragma unroll
    for (int r = ty; r < 32; r += 8)
        dst[(size_t)(n0 + r) * Kn + k0 + tx] = __float2half_rn(tile[tx][r]);
}

// ---------------- fused prep: LN1 + coalesced qkv pack + 3 weight transposes ----------
__global__ __launch_bounds__(256) void prep_k(
    const float* __restrict__ x, const float* __restrict__ ln1_g, const float* __restrict__ ln1_b,
    const float* __restrict__ Wq, const float* __restrict__ Wk, const float* __restrict__ Wv,
    const float* __restrict__ Wproj, const float* __restrict__ W1, const float* __restrict__ W2)
{
    __shared__ float tile[32][33];
    __shared__ float sh[64];
    int tid = threadIdx.x;
    int bid = blockIdx.x;

    if (bid < MROWS) {
        ln_body(x + (size_t)bid * C, ln1_g, ln1_b, g_xn + (size_t)bid * C, sh, tid);
    } else if (bid < MROWS + 3072) {
        int b2 = bid - MROWS;
        int mat = b2 >> 10;
        int rem = b2 & 1023;
        int h = rem >> 6;
        int kt = (rem & 63) >> 1;
        int dt = rem & 1;
        const float* W = (mat == 0) ? Wq : (mat == 1) ? Wk : Wv;
        int k0 = kt * 32, d0 = dt * 32;
        int tx = tid & 31, ty = tid >> 5;
        #pragma unroll
        for (int r = ty; r < 32; r += 8)
            tile[r][tx] = W[((size_t)h * C + k0 + r) * HD + d0 + tx];
        __syncthreads();
        #pragma unroll
        for (int r = ty; r < 32; r += 8) {
            int n = mat * 1024 + h * 64 + d0 + r;
            g_wqkvT[(size_t)n * C + k0 + tx] = __float2half_rn(tile[tx][r]);
        }
    } else if (bid < MROWS + 3072 + 1024) {
        int b2 = bid - (MROWS + 3072);
        tr_body(Wproj, g_wprojT, C, C, b2 & 31, b2 >> 5, tid, tile);
    } else if (bid < MROWS + 3072 + 1024 + 4096) {
        int b2 = bid - (MROWS + 3072 + 1024);
        tr_body(W1, g_w1T, C, FF, b2 & 127, b2 >> 7, tid, tile);
    } else {
        int b2 = bid - (MROWS + 3072 + 1024 + 4096);
        tr_body(W2, g_w2T, FF, C, b2 & 31, b2 >> 5, tid, tile);
    }
}
#define PREP_BLOCKS (MROWS + 3072 + 1024 + 4096 + 4096)

// ---------------- standalone LN (for LN2) ----------------
__global__ void layernorm_k(const float* __restrict__ x, const float* __restrict__ g,
                            const float* __restrict__ b, __half* __restrict__ out) {
    __shared__ float sh[64];
    ln_body(x + (size_t)blockIdx.x * C, g, b, out + (size_t)blockIdx.x * C, sh, threadIdx.x);
}

// ---------------- launch ----------------
extern "C" void kernel_launch(void* const* d_in, const int* in_sizes, int n_in,
                              void* d_out, int out_size) {
    const float* x      = (const float*)d_in[0];
    const float* ln1_g  = (const float*)d_in[1];
    const float* ln1_b  = (const float*)d_in[2];
    const float* ln2_g  = (const float*)d_in[3];
    const float* ln2_b  = (const float*)d_in[4];
    const float* Wq     = (const float*)d_in[5];
    const float* Wk     = (const float*)d_in[6];
    const float* Wv     = (const float*)d_in[7];
    const float* Wproj  = (const float*)d_in[8];
    const float* bproj  = (const float*)d_in[9];
    const float* W1     = (const float*)d_in[10];
    const float* b1     = (const float*)d_in[11];
    const float* W2     = (const float*)d_in[12];
    const float* b2     = (const float*)d_in[13];
    float* out = (float*)d_out;

    __half *p_wqkvT, *p_wprojT, *p_w1T, *p_w2T, *p_xn, *p_qkv, *p_att, *p_h;
    float* p_x1;
    cudaGetSymbolAddress((void**)&p_wqkvT,  g_wqkvT);
    cudaGetSymbolAddress((void**)&p_wprojT, g_wprojT);
    cudaGetSymbolAddress((void**)&p_w1T,    g_w1T);
    cudaGetSymbolAddress((void**)&p_w2T,    g_w2T);
    cudaGetSymbolAddress((void**)&p_xn,     g_xn);
    cudaGetSymbolAddress((void**)&p_qkv,    g_qkv);
    cudaGetSymbolAddress((void**)&p_att,    g_att);
    cudaGetSymbolAddress((void**)&p_x1,     g_x1);
    cudaGetSymbolAddress((void**)&p_h,      g_h);

    cudaFuncSetAttribute(gemm_h<0>, cudaFuncAttributeMaxDynamicSharedMemorySize, GEMM_SMEM);
    cudaFuncSetAttribute(gemm_h<2>, cudaFuncAttributeMaxDynamicSharedMemorySize, GEMM_SMEM);
    cudaFuncSetAttribute(gemm_h<3>, cudaFuncAttributeMaxDynamicSharedMemorySize, GEMM_SMEM);
    cudaFuncSetAttribute(flash_h,   cudaFuncAttributeMaxDynamicSharedMemorySize, FLASH_SMEM);

    // 1) fused prep: LN1 + coalesced pack + all weight transposes
    prep_k<<<PREP_BLOCKS, 256>>>(x, ln1_g, ln1_b, Wq, Wk, Wv, Wproj, W1, W2);
    // 2) QKV GEMM: [4096,1024] @ [1024,3072] -> half
    gemm_h<0><<<dim3(3 * C / 128, MROWS / 128), 256, GEMM_SMEM>>>(
        p_xn, p_wqkvT, p_qkv, C, 3 * C, nullptr, nullptr);
    // 3) fused flash attention -> att (half), 3-buffer KV, longest tiles first
    flash_h<<<dim3(T / 128, Bn * H), 256, FLASH_SMEM>>>(p_qkv, p_att);
    // 4) proj + bias + residual(x) -> x1 (fp32)
    gemm_h<3><<<dim3(C / 128, MROWS / 128), 256, GEMM_SMEM>>>(
        p_att, p_wprojT, p_x1, C, C, bproj, x);
    // 5) LN2 -> xn (half)
    layernorm_k<<<MROWS, 256>>>(p_x1, ln2_g, ln2_b, p_xn);
    // 6) FFN1 + bias + gelu -> h (half)
    gemm_h<2><<<dim3(FF / 128, MROWS / 128), 256, GEMM_SMEM>>>(
        p_xn, p_w1T, p_h, C, FF, b1, nullptr);
    // 7) FFN2 + bias + residual(x1) -> out (fp32)
    gemm_h<3><<<dim3(C / 128, MROWS / 128), 256, GEMM_SMEM>>>(
        p_h, p_w2T, out, FF, C, b2, p_x1);
}

// round 16
// speedup vs baseline: 1.1599x; 1.1118x over previous
#include <cuda_runtime.h>
#include <cuda_fp16.h>
#include <math.h>
#include <stdint.h>

#define Bn 4
#define T 1024
#define C 1024
#define H 16
#define HD 64
#define FF 4096
#define MROWS (Bn*T)   // 4096

// ---------------- scratch (device globals; no runtime allocation) ----------------
// weight buffers hold fragment-major packed B operands (same element count)
__device__ __align__(1024) __half g_wqkvF[3*C * C];               // qkv weights, frag-major
__device__ __align__(1024) __half g_wprojF[C * C];
__device__ __align__(1024) __half g_w1F[FF * C];
__device__ __align__(1024) __half g_w2F[C * FF];
__device__ __align__(1024) __half g_xn[MROWS * C];                // layernorm out
__device__ __align__(1024) __half g_qkv[(size_t)MROWS * 3 * C];   // [M, 3C]
__device__ __align__(1024) __half g_att[MROWS * C];               // attention out
__device__ __align__(1024) __half g_h[(size_t)MROWS * FF];        // FFN hidden
__device__ __align__(1024) float  g_x1[MROWS * C];                // x + attn_proj (fp32)

// ---------------- helpers ----------------
__device__ __forceinline__ uint32_t smem_u32(const void* p) {
    uint32_t a;
    asm("{ .reg .u64 t; cvta.to.shared.u64 t, %1; cvt.u32.u64 %0, t; }" : "=r"(a) : "l"(p));
    return a;
}

#define CP_ASYNC16(dst, src) \
    asm volatile("cp.async.cg.shared.global [%0], [%1], 16;" :: "r"(dst), "l"(src) : "memory")
#define CP_COMMIT() asm volatile("cp.async.commit_group;" ::: "memory")
#define CP_WAIT(n)  asm volatile("cp.async.wait_group %0;" :: "n"(n) : "memory")

#define LDSM4(r0, r1, r2, r3, addr) \
    asm volatile("ldmatrix.sync.aligned.m8n8.x4.shared.b16 {%0,%1,%2,%3}, [%4];" \
        : "=r"(r0), "=r"(r1), "=r"(r2), "=r"(r3) : "r"(addr))
#define LDSM4T(r0, r1, r2, r3, addr) \
    asm volatile("ldmatrix.sync.aligned.m8n8.x4.trans.shared.b16 {%0,%1,%2,%3}, [%4];" \
        : "=r"(r0), "=r"(r1), "=r"(r2), "=r"(r3) : "r"(addr))

__device__ __forceinline__ void mma_f16(float* d, const uint32_t* a, const uint32_t* b) {
    asm volatile(
        "mma.sync.aligned.m16n8k16.row.col.f32.f16.f16.f32 "
        "{%0,%1,%2,%3}, {%4,%5,%6,%7}, {%8,%9}, {%0,%1,%2,%3};"
        : "+f"(d[0]), "+f"(d[1]), "+f"(d[2]), "+f"(d[3])
        : "r"(a[0]), "r"(a[1]), "r"(a[2]), "r"(a[3]), "r"(b[0]), "r"(b[1]));
}
__device__ __forceinline__ uint32_t hmul2u(uint32_t a, uint32_t b) {
    __half2 r = __hmul2(*(__half2*)&a, *(__half2*)&b);
    return *(uint32_t*)&r;
}
__device__ __forceinline__ uint32_t f22h(float x, float y) {
    __half2 h = __floats2half2_rn(x, y);
    return *(uint32_t*)&h;
}

// ---------------- fp16 tensor-core GEMM with fragment-major B from GMEM -------------
// C[M,N] = A[M,K] @ B[N,K]^T.  A: SMEM via cp.async (128x64 tiles, 3 stages, 2 CTAs/SM).
// B: pre-packed fragment-major; one LDG.64 per lane per (ks, ni) — no SMEM, no LDSM.
// Frag layout: uint2 index = (nblk*(K/16) + kblk)*32 + lane; .x={B[2t][g],B[2t+1][g]},
// .y={B[2t+8][g],B[2t+9][g]}, t=lane%4, g=lane/4 (PTX m16n8k16 row.col B operand).
// EPI: 0 half out; 2 bias+gelu half out; 3 bias+resid(fp32) float out
#define PADH 72
#define STG 3
#define ATILE_H (128 * PADH)
#define GEMM_SMEM (STG * ATILE_H * 2)

template <int EPI>
__global__ __launch_bounds__(256, 2) void gemm_h(
    const __half* __restrict__ Ag, const __half* __restrict__ Bfrag, void* __restrict__ Cm,
    int Kn, int Nn,
    const float* __restrict__ bias, const float* __restrict__ resid)
{
    extern __shared__ __half smh[];
    __half* smA = smh;                    // [STG][128][PADH]
    int tid = threadIdx.x, lane = tid & 31, wid = tid >> 5;
    int bx = blockIdx.x, by = blockIdx.y;
    int wm = (wid >> 2) * 64, wn = (wid & 3) * 32;
    int lane16 = lane & 15, lanehi = lane >> 4;
    int lq = lane >> 2, lr = lane & 3;

    const int NT = Kn >> 6;               // 64-deep k-tiles
    const int KB = Kn >> 4;               // k16 blocks total
    const uint2* Bf = (const uint2*)Bfrag;
    const int nblk0 = (bx * 128 + wn) >> 3;

    // A loader: 16KB per tile = 1024 chunks, 4 per thread
    int crow = tid >> 1, ccol = (tid & 1) * 8;   // c = tid + i*256: row=c>>1? recompute below

    auto issueA = [&](int s, int kt) {
        const __half* As = Ag + (size_t)(by * 128) * Kn + kt * 64;
        uint32_t dA = smem_u32(smA + s * ATILE_H);
        #pragma unroll
        for (int i = 0; i < 4; i++) {
            int c = tid + i * 256;
            int r = c >> 3, col = (c & 7) * 8;
            CP_ASYNC16(dA + (r * PADH + col) * 2, As + (size_t)r * Kn + col);
        }
    };
    (void)crow; (void)ccol;

    float acc[4][4][4];
    #pragma unroll
    for (int mi = 0; mi < 4; mi++)
        #pragma unroll
        for (int ni = 0; ni < 4; ni++)
            #pragma unroll
            for (int q = 0; q < 4; q++) acc[mi][ni][q] = 0.f;

    #pragma unroll
    for (int s = 0; s < STG - 1; s++) { issueA(s, s); CP_COMMIT(); }
    CP_WAIT(STG - 2);
    __syncthreads();

    int aoff = (wm + lane16) * PADH + lanehi * 8;

    for (int kt = 0; kt < NT; kt++) {
        int nx = kt + STG - 1;
        if (nx < NT) issueA(nx % STG, nx);
        CP_COMMIT();

        const __half* At = smA + (kt % STG) * ATILE_H;
        const int kblk0 = kt * 4;

        #pragma unroll
        for (int ks = 0; ks < 4; ks++) {
            int k0 = ks * 16;
            // B fragments direct from GMEM (L2-hot), one LDG.64 per ni
            uint32_t b[4][2];
            #pragma unroll
            for (int ni = 0; ni < 4; ni++) {
                uint2 v = Bf[((size_t)(nblk0 + ni) * KB + kblk0 + ks) * 32 + lane];
                b[ni][0] = v.x; b[ni][1] = v.y;
            }
            uint32_t a[4][4];
            #pragma unroll
            for (int mi = 0; mi < 4; mi++) {
                uint32_t ad = smem_u32(At + aoff + mi * 16 * PADH + k0);
                LDSM4(a[mi][0], a[mi][1], a[mi][2], a[mi][3], ad);
            }
            #pragma unroll
            for (int mi = 0; mi < 4; mi++)
                #pragma unroll
                for (int ni = 0; ni < 4; ni++)
                    mma_f16(acc[mi][ni], a[mi], b[ni]);
        }

        CP_WAIT(STG - 2);
        __syncthreads();
    }

    #pragma unroll
    for (int ni = 0; ni < 4; ni++) {
        int c = bx * 128 + wn + ni * 8 + lr * 2;
        float b0 = 0.f, b1 = 0.f;
        if (EPI >= 1) { b0 = bias[c]; b1 = bias[c + 1]; }
        #pragma unroll
        for (int mi = 0; mi < 4; mi++) {
            int r0 = by * 128 + wm + mi * 16 + lq;
            #pragma unroll
            for (int half_ = 0; half_ < 2; half_++) {
                int r = r0 + half_ * 8;
                float v0 = acc[mi][ni][half_ * 2 + 0] + b0;
                float v1 = acc[mi][ni][half_ * 2 + 1] + b1;
                if (EPI == 2) {
                    v0 = 0.5f * v0 * (1.0f + erff(v0 * 0.70710678118654752440f));
                    v1 = 0.5f * v1 * (1.0f + erff(v1 * 0.70710678118654752440f));
                }
                if (EPI == 3) {
                    float2 rr = *(const float2*)(resid + (size_t)r * Nn + c);
                    *(float2*)((float*)Cm + (size_t)r * Nn + c) = make_float2(v0 + rr.x, v1 + rr.y);
                } else {
                    *(__half2*)((__half*)Cm + (size_t)r * Nn + c) = __floats2half2_rn(v0, v1);
                }
            }
        }
    }
}

// ---------------- fp16 flash attention (R15 best: 3-buffer KV, one sync/iter) --------
#define FQP 72
#define FKT (64 * FQP)
#define FLASH_SMEM ((128 * FQP + 3 * FKT + 3 * FKT) * 2)

__global__ __launch_bounds__(256, 2) void flash_h(const __half* __restrict__ qkv,
                                                  __half* __restrict__ att) {
    extern __shared__ __half smh[];
    __half* Qs = smh;
    __half* Ks = smh + 128 * FQP;
    __half* Vs = Ks + 3 * FKT;

    int tid = threadIdx.x, lane = tid & 31, w = tid >> 5;
    int lane16 = lane & 15, lanehi = lane >> 4;
    int lq = lane >> 2, lr = lane & 3;
    int qt = (int)(gridDim.x - 1 - blockIdx.x);
    int bh = blockIdx.y;
    int b = bh >> 4, h = bh & 15;
    const int ktiles = 2 * qt + 2;

    auto issueQ = [&]() {
        uint32_t dQ = smem_u32(Qs);
        #pragma unroll
        for (int i = 0; i < 4; i++) {
            int c = tid + i * 256;
            int row = c >> 3, col = (c & 7) * 8;
            const __half* src = qkv + (size_t)(b * T + qt * 128 + row) * 3072 + h * 64 + col;
            CP_ASYNC16(dQ + (row * FQP + col) * 2, src);
        }
    };
    auto issueKV = [&](int kt, int buf) {
        uint32_t dK = smem_u32(Ks + buf * FKT);
        uint32_t dV = smem_u32(Vs + buf * FKT);
        #pragma unroll
        for (int i = 0; i < 2; i++) {
            int c = tid + i * 256;
            int row = c >> 3, col = (c & 7) * 8;
            size_t gr = (size_t)(b * T + kt * 64 + row) * 3072 + h * 64 + col;
            CP_ASYNC16(dK + (row * FQP + col) * 2, qkv + gr + 1024);
            CP_ASYNC16(dV + (row * FQP + col) * 2, qkv + gr + 2048);
        }
    };

    issueQ(); issueKV(0, 0); CP_COMMIT();
    issueKV(1, 1); CP_COMMIT();
    CP_WAIT(1);
    __syncthreads();

    uint32_t qf[4][4];
    {
        __half2 s8 = __float2half2_rn(0.125f);
        uint32_t s8u = *(uint32_t*)&s8;
        #pragma unroll
        for (int ks = 0; ks < 4; ks++) {
            uint32_t ad = smem_u32(Qs + (w * 16 + lane16) * FQP + ks * 16 + lanehi * 8);
            LDSM4(qf[ks][0], qf[ks][1], qf[ks][2], qf[ks][3], ad);
            #pragma unroll
            for (int j = 0; j < 4; j++) qf[ks][j] = hmul2u(qf[ks][j], s8u);
        }
    }

    float oacc[8][4];
    #pragma unroll
    for (int ni = 0; ni < 8; ni++)
        #pragma unroll
        for (int q = 0; q < 4; q++) oacc[ni][q] = 0.f;
    float m0 = -1e30f, m1 = -1e30f, l0 = 0.f, l1 = 0.f;

    const int gr0 = qt * 128 + w * 16 + lq;
    const int gr1 = gr0 + 8;

    for (int kt = 0; kt < ktiles; kt++) {
        if (kt > 0) { CP_WAIT(1); __syncthreads(); }
        if (kt + 2 < ktiles) issueKV(kt + 2, (kt + 2) % 3);
        CP_COMMIT();

        const __half* K = Ks + (kt % 3) * FKT;
        const __half* V = Vs + (kt % 3) * FKT;

        float sacc[8][4];
        #pragma unroll
        for (int ni = 0; ni < 8; ni++)
            #pragma unroll
            for (int q = 0; q < 4; q++) sacc[ni][q] = 0.f;
        #pragma unroll
        for (int ks = 0; ks < 4; ks++) {
            int k0 = ks * 16;
            #pragma unroll
            for (int nb = 0; nb < 4; nb++) {
                uint32_t m0r, m1r, m2r, m3r;
                uint32_t ad = smem_u32(K + (nb * 16 + lane16) * FQP + k0 + lanehi * 8);
                LDSM4(m0r, m1r, m2r, m3r, ad);
                uint32_t blo[2] = {m0r, m2r}, bhi[2] = {m1r, m3r};
                mma_f16(sacc[2 * nb], qf[ks], blo);
                mma_f16(sacc[2 * nb + 1], qf[ks], bhi);
            }
        }

        if (kt >= 2 * qt) {
            #pragma unroll
            for (int ni = 0; ni < 8; ni++) {
                int cbase = kt * 64 + ni * 8 + lr * 2;
                #pragma unroll
                for (int j = 0; j < 2; j++) {
                    if (cbase + j > gr0) sacc[ni][j]     = -1e30f;
                    if (cbase + j > gr1) sacc[ni][2 + j] = -1e30f;
                }
            }
        }

        float mx0 = -1e30f, mx1 = -1e30f;
        #pragma unroll
        for (int ni = 0; ni < 8; ni++) {
            mx0 = fmaxf(mx0, fmaxf(sacc[ni][0], sacc[ni][1]));
            mx1 = fmaxf(mx1, fmaxf(sacc[ni][2], sacc[ni][3]));
        }
        #pragma unroll
        for (int off = 1; off <= 2; off <<= 1) {
            mx0 = fmaxf(mx0, __shfl_xor_sync(0xffffffffu, mx0, off));
            mx1 = fmaxf(mx1, __shfl_xor_sync(0xffffffffu, mx1, off));
        }
        float mn0 = fmaxf(m0, mx0), mn1 = fmaxf(m1, mx1);
        float al0 = __expf(m0 - mn0), al1 = __expf(m1 - mn1);
        m0 = mn0; m1 = mn1;
        float s0 = 0.f, s1 = 0.f;
        #pragma unroll
        for (int ni = 0; ni < 8; ni++) {
            sacc[ni][0] = __expf(sacc[ni][0] - mn0);
            sacc[ni][1] = __expf(sacc[ni][1] - mn0);
            sacc[ni][2] = __expf(sacc[ni][2] - mn1);
            sacc[ni][3] = __expf(sacc[ni][3] - mn1);
            s0 += sacc[ni][0] + sacc[ni][1];
            s1 += sacc[ni][2] + sacc[ni][3];
        }
        #pragma unroll
        for (int off = 1; off <= 2; off <<= 1) {
            s0 += __shfl_xor_sync(0xffffffffu, s0, off);
            s1 += __shfl_xor_sync(0xffffffffu, s1, off);
        }
        l0 = l0 * al0 + s0;
        l1 = l1 * al1 + s1;
        #pragma unroll
        for (int ni = 0; ni < 8; ni++) {
            oacc[ni][0] *= al0; oacc[ni][1] *= al0;
            oacc[ni][2] *= al1; oacc[ni][3] *= al1;
        }

        #pragma unroll
        for (int kk = 0; kk < 4; kk++) {
            uint32_t a[4];
            a[0] = f22h(sacc[2 * kk][0], sacc[2 * kk][1]);
            a[1] = f22h(sacc[2 * kk][2], sacc[2 * kk][3]);
            a[2] = f22h(sacc[2 * kk + 1][0], sacc[2 * kk + 1][1]);
            a[3] = f22h(sacc[2 * kk + 1][2], sacc[2 * kk + 1][3]);
            #pragma unroll
            for (int dbp = 0; dbp < 4; dbp++) {
                uint32_t m0r, m1r, m2r, m3r;
                uint32_t ad = smem_u32(V + (kk * 16 + lane16) * FQP + dbp * 16 + lanehi * 8);
                LDSM4T(m0r, m1r, m2r, m3r, ad);
                uint32_t blo[2] = {m0r, m1r}, bhi[2] = {m2r, m3r};
                mma_f16(oacc[2 * dbp], a, blo);
                mma_f16(oacc[2 * dbp + 1], a, bhi);
            }
        }
    }

    float inv0 = 1.0f / l0, inv1 = 1.0f / l1;
    size_t ro0 = ((size_t)(b * T) + gr0) * 1024 + h * 64;
    size_t ro1 = ((size_t)(b * T) + gr1) * 1024 + h * 64;
    #pragma unroll
    for (int ni = 0; ni < 8; ni++) {
        int cc = ni * 8 + lr * 2;
        *(__half2*)(att + ro0 + cc) = __floats2half2_rn(oacc[ni][0] * inv0, oacc[ni][1] * inv0);
        *(__half2*)(att + ro1 + cc) = __floats2half2_rn(oacc[ni][2] * inv1, oacc[ni][3] * inv1);
    }
}

// ---------------- LN body (device) ----------------
__device__ __forceinline__ void ln_body(const float* xr, const float* g, const float* b,
                                        __half* yr, float* sh, int tid) {
    float s = 0.f, s2 = 0.f;
    for (int i = tid; i < C; i += 256) {
        float v = xr[i]; s += v; s2 += v * v;
    }
    int lid = tid & 31, wid = tid >> 5;
    #pragma unroll
    for (int o = 16; o > 0; o >>= 1) {
        s  += __shfl_xor_sync(0xffffffffu, s,  o);
        s2 += __shfl_xor_sync(0xffffffffu, s2, o);
    }
    if (lid == 0) { sh[wid] = s; sh[wid + 32] = s2; }
    __syncthreads();
    if (tid == 0) {
        float a = 0.f, a2 = 0.f;
        for (int w = 0; w < 8; w++) { a += sh[w]; a2 += sh[w + 32]; }
        sh[0] = a; sh[1] = a2;
    }
    __syncthreads();
    float mean = sh[0] * (1.0f / C);
    float var  = sh[1] * (1.0f / C) - mean * mean;
    float rstd = rsqrtf(var + 1e-5f);
    for (int i = tid; i < C; i += 256)
        yr[i] = __float2half_rn((xr[i] - mean) * rstd * g[i] + b[i]);
}

// ---------------- fragment pack body: src fp32 [Ktot rows, row-stride rs], tile at
// (k0, src col base), dst frag buffer with global n base. Tile = 64k x 64n. -----------
__device__ __forceinline__ void fp_body(const float* __restrict__ src, size_t rs,
                                        uint2* __restrict__ dst,
                                        int KB, int k0, int nblk_base,
                                        int tid, float (*s)[65]) {
    // load 64x64 source tile (rows k contiguous in src cols) — coalesced
    for (int i = tid; i < 64 * 64; i += 256) {
        int r = i >> 6, c = i & 63;
        s[r][c] = src[(size_t)(k0 + r) * rs + c];
    }
    __syncthreads();
    // write 32 fragments x 32 lanes, 4 lane-slots per thread
    #pragma unroll
    for (int j = 0; j < 4; j++) {
        int idx = tid + j * 256;
        int frag = idx >> 5, lane = idx & 31;
        int nl = (frag & 7) * 8 + (lane >> 2);
        int kl = (frag >> 3) * 16 + (lane & 3) * 2;
        __half h0 = __float2half_rn(s[kl][nl]);
        __half h1 = __float2half_rn(s[kl + 1][nl]);
        __half h2 = __float2half_rn(s[kl + 8][nl]);
        __half h3 = __float2half_rn(s[kl + 9][nl]);
        uint2 v;
        v.x = (uint32_t)__half_as_ushort(h0) | ((uint32_t)__half_as_ushort(h1) << 16);
        v.y = (uint32_t)__half_as_ushort(h2) | ((uint32_t)__half_as_ushort(h3) << 16);
        int nblk = nblk_base + (frag & 7);
        int kblk = (k0 >> 4) + (frag >> 3);
        dst[((size_t)nblk * KB + kblk) * 32 + lane] = v;
    }
    __syncthreads();
}

// ---------------- fused prep: LN1 + fragment packs for all weights ----------
// blocks: [0,4096) LN1 | [4096,4864) qkv (3*16*16) | [4864,5120) proj (16*16)
//       | [5120,6144) W1 (64*16) | [6144,7168) W2 (16*64)
__global__ __launch_bounds__(256) void prep_k(
    const float* __restrict__ x, const float* __restrict__ ln1_g, const float* __restrict__ ln1_b,
    const float* __restrict__ Wq, const float* __restrict__ Wk, const float* __restrict__ Wv,
    const float* __restrict__ Wproj, const float* __restrict__ W1, const float* __restrict__ W2)
{
    __shared__ float tile[64][65];
    __shared__ float sh[64];
    int tid = threadIdx.x;
    int bid = blockIdx.x;

    if (bid < MROWS) {
        ln_body(x + (size_t)bid * C, ln1_g, ln1_b, g_xn + (size_t)bid * C, sh, tid);
    } else if (bid < MROWS + 768) {
        // qkv: per (mat, h, ktile): src W[h][k][d] 64x64 tile; n base = mat*1024 + h*64
        int b2 = bid - MROWS;
        int mat = b2 / 256;
        int rem = b2 % 256;
        int h = rem >> 4;
        int kt = rem & 15;
        const float* W = (mat == 0) ? Wq : (mat == 1) ? Wk : Wv;
        fp_body(W + (size_t)h * C * HD, HD, (uint2*)g_wqkvF, C >> 4, kt * 64,
                (mat * 1024 + h * 64) >> 3, tid, tile);
    } else if (bid < MROWS + 768 + 256) {
        int b2 = bid - (MROWS + 768);
        int nt = b2 & 15, kt = b2 >> 4;
        fp_body(Wproj + nt * 64, C, (uint2*)g_wprojF, C >> 4, kt * 64, nt * 8, tid, tile);
    } else if (bid < MROWS + 768 + 256 + 1024) {
        int b2 = bid - (MROWS + 768 + 256);
        int nt = b2 & 63, kt = b2 >> 6;
        fp_body(W1 + nt * 64, FF, (uint2*)g_w1F, C >> 4, kt * 64, nt * 8, tid, tile);
    } else {
        int b2 = bid - (MROWS + 768 + 256 + 1024);
        int nt = b2 & 15, kt = b2 >> 4;
        fp_body(W2 + nt * 64, C, (uint2*)g_w2F, FF >> 4, kt * 64, nt * 8, tid, tile);
    }
}
#define PREP_BLOCKS (MROWS + 768 + 256 + 1024 + 1024)

// ---------------- standalone LN (for LN2) ----------------
__global__ void layernorm_k(const float* __restrict__ x, const float* __restrict__ g,
                            const float* __restrict__ b, __half* __restrict__ out) {
    __shared__ float sh[64];
    ln_body(x + (size_t)blockIdx.x * C, g, b, out + (size_t)blockIdx.x * C, sh, threadIdx.x);
}

// ---------------- launch ----------------
extern "C" void kernel_launch(void* const* d_in, const int* in_sizes, int n_in,
                              void* d_out, int out_size) {
    const float* x      = (const float*)d_in[0];
    const float* ln1_g  = (const float*)d_in[1];
    const float* ln1_b  = (const float*)d_in[2];
    const float* ln2_g  = (const float*)d_in[3];
    const float* ln2_b  = (const float*)d_in[4];
    const float* Wq     = (const float*)d_in[5];
    const float* Wk     = (const float*)d_in[6];
    const float* Wv     = (const float*)d_in[7];
    const float* Wproj  = (const float*)d_in[8];
    const float* bproj  = (const float*)d_in[9];
    const float* W1     = (const float*)d_in[10];
    const float* b1     = (const float*)d_in[11];
    const float* W2     = (const float*)d_in[12];
    const float* b2     = (const float*)d_in[13];
    float* out = (float*)d_out;

    __half *p_wqkvF, *p_wprojF, *p_w1F, *p_w2F, *p_xn, *p_qkv, *p_att, *p_h;
    float* p_x1;
    cudaGetSymbolAddress((void**)&p_wqkvF,  g_wqkvF);
    cudaGetSymbolAddress((void**)&p_wprojF, g_wprojF);
    cudaGetSymbolAddress((void**)&p_w1F,    g_w1F);
    cudaGetSymbolAddress((void**)&p_w2F,    g_w2F);
    cudaGetSymbolAddress((void**)&p_xn,     g_xn);
    cudaGetSymbolAddress((void**)&p_qkv,    g_qkv);
    cudaGetSymbolAddress((void**)&p_att,    g_att);
    cudaGetSymbolAddress((void**)&p_x1,     g_x1);
    cudaGetSymbolAddress((void**)&p_h,      g_h);

    cudaFuncSetAttribute(gemm_h<0>, cudaFuncAttributeMaxDynamicSharedMemorySize, GEMM_SMEM);
    cudaFuncSetAttribute(gemm_h<2>, cudaFuncAttributeMaxDynamicSharedMemorySize, GEMM_SMEM);
    cudaFuncSetAttribute(gemm_h<3>, cudaFuncAttributeMaxDynamicSharedMemorySize, GEMM_SMEM);
    cudaFuncSetAttribute(flash_h,   cudaFuncAttributeMaxDynamicSharedMemorySize, FLASH_SMEM);

    // 1) fused prep: LN1 + fragment-pack all weights
    prep_k<<<PREP_BLOCKS, 256>>>(x, ln1_g, ln1_b, Wq, Wk, Wv, Wproj, W1, W2);
    // 2) QKV GEMM: [4096,1024] @ [1024,3072] -> half
    gemm_h<0><<<dim3(3 * C / 128, MROWS / 128), 256, GEMM_SMEM>>>(
        p_xn, p_wqkvF, p_qkv, C, 3 * C, nullptr, nullptr);
    // 3) fused flash attention -> att (half)
    flash_h<<<dim3(T / 128, Bn * H), 256, FLASH_SMEM>>>(p_qkv, p_att);
    // 4) proj + bias + residual(x) -> x1 (fp32)
    gemm_h<3><<<dim3(C / 128, MROWS / 128), 256, GEMM_SMEM>>>(
        p_att, p_wprojF, p_x1, C, C, bproj, x);
    // 5) LN2 -> xn (half)
    layernorm_k<<<MROWS, 256>>>(p_x1, ln2_g, ln2_b, p_xn);
    // 6) FFN1 + bias + gelu -> h (half)
    gemm_h<2><<<dim3(FF / 128, MROWS / 128), 256, GEMM_SMEM>>>(
        p_xn, p_w1F, p_h, C, FF, b1, nullptr);
    // 7) FFN2 + bias + residual(x1) -> out (fp32)
    gemm_h<3><<<dim3(C / 128, MROWS / 128), 256, GEMM_SMEM>>>(
        p_h, p_w2F, out, FF, C, b2, p_x1);
}